// round 1
// baseline (speedup 1.0000x reference)
#include <cuda_runtime.h>
#include <float.h>
#include <math.h>

// Problem constants (shapes fixed by the dataset)
#define DIM       256
#define MAXB      128
#define TOPK      32
#define CAND_CAP  65536

#define INV_TAU   10.0f     // 1 / 0.1
#define PEN_COEF  0.25f     // BETA / (2*SIGMA^2) = 0.5 / 2
#define SIM_BOUND 10.0f     // max |q.K| / tau  (q, K unit-norm)

// ---------------- scratch (device globals; no allocation allowed) ----------
__device__ int   g_count;
__device__ float g_thresh;
__device__ int   g_cidx[CAND_CAP];
__device__ float g_cpen[CAND_CAP];
__device__ float g_qn[MAXB * DIM];
__device__ float g_logits[(size_t)MAXB * CAND_CAP];   // 32 MB

// ---------------------------------------------------------------------------
// Kernel 1: compute sound candidate threshold.
// Partition rows into 32 groups by (n mod 32); the max over the 32 per-group
// minimum penalties is an upper bound on the 32nd-smallest penalty p32
// (32 distinct rows -> their max >= p32). thresh = bound + 2*SIM_BOUND + margin.
// Also resets the candidate counter.
// ---------------------------------------------------------------------------
__global__ void k_thresh(const float* __restrict__ times,
                         const float* __restrict__ qtime, int N) {
    __shared__ float s[1024];
    int tid = threadIdx.x;
    if (tid == 0) g_count = 0;
    float qt = qtime[0];
    float lmin = FLT_MAX;
    for (int n = tid; n < N; n += 1024) {        // 1024 % 32 == 0 -> fixed residue
        float dt = qt - times[n];
        float p = PEN_COEF * dt * dt;
        lmin = fminf(lmin, p);
    }
    s[tid] = lmin;
    __syncthreads();
    if (tid < 32) {                               // reduce each residue group
        float gm = FLT_MAX;
        #pragma unroll
        for (int j = 0; j < 32; j++) gm = fminf(gm, s[tid + 32 * j]);
        s[tid] = gm;
    }
    __syncthreads();
    if (tid == 0) {
        float mx = -FLT_MAX;
        #pragma unroll
        for (int g = 0; g < 32; g++) mx = fmaxf(mx, s[g]);
        g_thresh = mx + 2.0f * SIM_BOUND + 4.0f;  // +4 fp safety margin
    }
}

// ---------------------------------------------------------------------------
// Kernel 2: L2-normalize queries (matches F.normalize with eps=1e-12).
// ---------------------------------------------------------------------------
__global__ void k_norm(const float* __restrict__ query, int B) {
    __shared__ float red[DIM];
    int b = blockIdx.x;
    int tid = threadIdx.x;
    float v = query[b * DIM + tid];
    red[tid] = v * v;
    __syncthreads();
    for (int s = DIM / 2; s > 0; s >>= 1) {
        if (tid < s) red[tid] += red[tid + s];
        __syncthreads();
    }
    float nrm = fmaxf(sqrtf(red[0]), 1e-12f);
    g_qn[b * DIM + tid] = v / nrm;
}

// ---------------------------------------------------------------------------
// Kernel 3: compact candidate rows (penalty <= thresh).
// ---------------------------------------------------------------------------
__global__ void k_compact(const float* __restrict__ times,
                          const float* __restrict__ qtime, int N) {
    int n = blockIdx.x * blockDim.x + threadIdx.x;
    if (n >= N) return;
    float qt = qtime[0];
    float dt = qt - times[n];
    float p = PEN_COEF * dt * dt;
    if (p <= g_thresh) {
        int pos = atomicAdd(&g_count, 1);
        if (pos < CAND_CAP) { g_cidx[pos] = n; g_cpen[pos] = p; }
    }
}

// ---------------------------------------------------------------------------
// Kernel 4: exact fp32 logits for all queries x candidates.
// Block = (candidate chunk x query group of 32). q tile transposed in SMEM,
// 8 K rows staged per iteration. 256 thr = 8 cands x 32 queries.
// ---------------------------------------------------------------------------
__global__ void k_logits(const float* __restrict__ Kbank, int B) {
    __shared__ float qs[DIM * 32];   // qs[d*32 + j]  (32 KB)
    __shared__ float kv[8 * DIM];    // 8 candidate K rows (8 KB)

    int tid = threadIdx.x;
    int grp = blockIdx.y;            // query group (32 queries each)
    int cnt = min(g_count, CAND_CAP);

    // load 32 queries, transposed
    for (int i = tid; i < 32 * DIM; i += 256) {
        int j = i & 31, d = i >> 5;
        int b = grp * 32 + j;
        qs[i] = (b < B) ? g_qn[b * DIM + d] : 0.0f;
    }
    __syncthreads();

    for (int m0 = blockIdx.x * 8; m0 < cnt; m0 += gridDim.x * 8) {
        #pragma unroll
        for (int r = 0; r < 8; r++) {
            int m = m0 + r;
            int c = (m < cnt) ? g_cidx[m] : g_cidx[m0];
            kv[r * DIM + tid] = Kbank[(size_t)c * DIM + tid];
        }
        __syncthreads();

        int ci = tid >> 5;           // candidate within chunk (uniform per warp)
        int jq = tid & 31;           // query within group
        int m  = m0 + ci;
        int b  = grp * 32 + jq;
        if (m < cnt && b < B) {
            const float* kr = kv + ci * DIM;
            float acc = 0.0f;
            #pragma unroll 8
            for (int d = 0; d < DIM; d++)
                acc += qs[d * 32 + jq] * kr[d];
            g_logits[(size_t)b * CAND_CAP + m] = acc * INV_TAU - g_cpen[m];
        }
        __syncthreads();
    }
}

// ---------------------------------------------------------------------------
// Kernel 5: per-query top-32 (iterative argmax over candidates), softmax,
// attention-weighted V gather. One block per query, 256 threads (= DIM).
// ---------------------------------------------------------------------------
__global__ void k_select(const float* __restrict__ Vbank,
                         float* __restrict__ out, int B) {
    __shared__ float rv[8];
    __shared__ int   ri[8];
    __shared__ float sv[TOPK];
    __shared__ int   si[TOPK];

    int b   = blockIdx.x;
    int tid = threadIdx.x;
    int cnt = min(g_count, CAND_CAP);
    float* row = g_logits + (size_t)b * CAND_CAP;

    int lane = tid & 31, warp = tid >> 5;

    for (int k = 0; k < TOPK; k++) {
        float best = -FLT_MAX; int bidx = 0x7FFFFFFF;
        for (int m = tid; m < cnt; m += 256) {
            float v = row[m];
            if (v > best || (v == best && m < bidx)) { best = v; bidx = m; }
        }
        // warp argmax (prefer lower index on tie)
        #pragma unroll
        for (int off = 16; off > 0; off >>= 1) {
            float ov = __shfl_down_sync(0xFFFFFFFFu, best, off);
            int   oi = __shfl_down_sync(0xFFFFFFFFu, bidx, off);
            if (ov > best || (ov == best && oi < bidx)) { best = ov; bidx = oi; }
        }
        if (lane == 0) { rv[warp] = best; ri[warp] = bidx; }
        __syncthreads();
        if (tid == 0) {
            float bb = rv[0]; int bi = ri[0];
            #pragma unroll
            for (int w = 1; w < 8; w++)
                if (rv[w] > bb || (rv[w] == bb && ri[w] < bi)) { bb = rv[w]; bi = ri[w]; }
            sv[k] = bb;
            si[k] = g_cidx[bi];
            row[bi] = -FLT_MAX;       // exclude from next rounds
        }
        __syncthreads();
    }

    // softmax over the 32 selected logits (warp 0)
    if (tid < 32) {
        float v = sv[tid];
        float mx = v;
        #pragma unroll
        for (int off = 16; off > 0; off >>= 1)
            mx = fmaxf(mx, __shfl_xor_sync(0xFFFFFFFFu, mx, off));
        float e = expf(v - mx);
        float s = e;
        #pragma unroll
        for (int off = 16; off > 0; off >>= 1)
            s += __shfl_xor_sync(0xFFFFFFFFu, s, off);
        sv[tid] = e / s;
    }
    __syncthreads();

    // gather: out[b, d] = sum_k attn[k] * V[idx_k, d]   (tid == d)
    float acc = 0.0f;
    #pragma unroll
    for (int k = 0; k < TOPK; k++)
        acc += sv[k] * Vbank[(size_t)si[k] * DIM + tid];
    out[b * DIM + tid] = acc;
}

// ---------------------------------------------------------------------------
extern "C" void kernel_launch(void* const* d_in, const int* in_sizes, int n_in,
                              void* d_out, int out_size) {
    const float* query = (const float*)d_in[0];
    const float* Kbank = (const float*)d_in[1];
    const float* Vbank = (const float*)d_in[2];
    const float* times = (const float*)d_in[3];
    const float* qtime = (const float*)d_in[4];
    float* out = (float*)d_out;

    int B = in_sizes[0] / DIM;
    int N = in_sizes[3];

    k_thresh<<<1, 1024>>>(times, qtime, N);
    k_norm<<<B, DIM>>>(query, B);
    k_compact<<<(N + 255) / 256, 256>>>(times, qtime, N);
    dim3 g3(40, (B + 31) / 32);
    k_logits<<<g3, 256>>>(Kbank, B);
    k_select<<<B, DIM>>>(Vbank, out, B);
}

// round 2
// speedup vs baseline: 1.6091x; 1.6091x over previous
#include <cuda_runtime.h>
#include <float.h>
#include <math.h>

// Problem constants (shapes fixed by the dataset)
#define DIM       256
#define MAXB      128
#define TOPK      32
#define CAND_CAP  65536

#define INV_TAU   10.0f     // 1 / 0.1
#define PEN_COEF  0.25f     // BETA / (2*SIGMA^2) = 0.5 / 2
#define SIM_BOUND 10.0f     // max |q.K| / tau  (q, K unit-norm)

#define QG 64               // queries per logits block
#define CG 64               // candidates per logits chunk
#define SROWCAP 11776       // smem-cached row capacity for k_select (46 KB)

// ---------------- scratch (device globals; no allocation allowed) ----------
__device__ int          g_count;
__device__ float        g_thresh;
__device__ unsigned int g_gmin_bits[32];
__device__ int          g_cidx[CAND_CAP];
__device__ float        g_cpen[CAND_CAP];
__device__ float        g_qn[MAXB * DIM];
__device__ float        g_logits[(size_t)MAXB * CAND_CAP];   // 32 MB

// ---------------------------------------------------------------------------
// Kernel 0: reset counter + per-residue minima.
// ---------------------------------------------------------------------------
__global__ void k_init() {
    if (threadIdx.x == 0) g_count = 0;
    g_gmin_bits[threadIdx.x] = __float_as_uint(FLT_MAX);
}

// ---------------------------------------------------------------------------
// Kernel 1: grid-wide per-residue-group penalty minima.
// Rows are partitioned into 32 disjoint groups by (n & 31); with blockDim=256
// and gridDim*256 a multiple of 32, each thread's residue is fixed = tid&31.
// max over the 32 per-group minima >= 32nd-smallest penalty (32 distinct rows).
// atomicMin on uint bits is order-preserving for non-negative floats.
// ---------------------------------------------------------------------------
__global__ void k_minscan(const float* __restrict__ times,
                          const float* __restrict__ qtime, int N) {
    __shared__ float s[256];
    float qt = qtime[0];
    float lmin = FLT_MAX;
    int stride = gridDim.x * blockDim.x;
    for (int n = blockIdx.x * blockDim.x + threadIdx.x; n < N; n += stride) {
        float dt = qt - times[n];
        lmin = fminf(lmin, PEN_COEF * dt * dt);
    }
    s[threadIdx.x] = lmin;
    __syncthreads();
    if (threadIdx.x < 32) {
        float m = s[threadIdx.x];
        #pragma unroll
        for (int w = 1; w < 8; w++) m = fminf(m, s[w * 32 + threadIdx.x]);
        atomicMin(&g_gmin_bits[threadIdx.x], __float_as_uint(m));
    }
}

// ---------------------------------------------------------------------------
// Kernel 2: finalize threshold (1 warp).
// ---------------------------------------------------------------------------
__global__ void k_fin() {
    float v = __uint_as_float(g_gmin_bits[threadIdx.x]);
    #pragma unroll
    for (int off = 16; off > 0; off >>= 1)
        v = fmaxf(v, __shfl_xor_sync(0xFFFFFFFFu, v, off));
    if (threadIdx.x == 0)
        g_thresh = v + 2.0f * SIM_BOUND + 4.0f;   // sound bound + fp margin
}

// ---------------------------------------------------------------------------
// Kernel 3: L2-normalize queries (matches F.normalize with eps=1e-12).
// ---------------------------------------------------------------------------
__global__ void k_norm(const float* __restrict__ query, int B) {
    __shared__ float red[DIM];
    int b = blockIdx.x;
    int tid = threadIdx.x;
    float v = query[b * DIM + tid];
    red[tid] = v * v;
    __syncthreads();
    for (int s = DIM / 2; s > 0; s >>= 1) {
        if (tid < s) red[tid] += red[tid + s];
        __syncthreads();
    }
    float nrm = fmaxf(sqrtf(red[0]), 1e-12f);
    g_qn[b * DIM + tid] = v / nrm;
}

// ---------------------------------------------------------------------------
// Kernel 4: compact candidate rows (penalty <= thresh).
// ---------------------------------------------------------------------------
__global__ void k_compact(const float* __restrict__ times,
                          const float* __restrict__ qtime, int N) {
    int n = blockIdx.x * blockDim.x + threadIdx.x;
    if (n >= N) return;
    float qt = qtime[0];
    float dt = qt - times[n];
    float p = PEN_COEF * dt * dt;
    if (p <= g_thresh) {
        int pos = atomicAdd(&g_count, 1);
        if (pos < CAND_CAP) { g_cidx[pos] = n; g_cpen[pos] = p; }
    }
}

// ---------------------------------------------------------------------------
// Kernel 5: exact fp32 logits, register-tiled.
// Block tile: QG=64 queries x CG=64 candidates per chunk. 256 threads, each
// computing a 4x4 register tile. Both operands stored transposed in dynamic
// SMEM ([d][col], stride 64) so the inner d-step is 2x LDS.128 + 16 FMA.
// Store mapping (col = lane within warp) keeps SMEM writes conflict-free.
// ---------------------------------------------------------------------------
extern __shared__ float s_dyn[];   // qs[DIM*QG] then kv[DIM*CG]

__global__ void __launch_bounds__(256, 1)
k_logits(const float* __restrict__ Kbank, int B) {
    float* qs = s_dyn;             // [d*QG + q]
    float* kv = s_dyn + DIM * QG;  // [d*CG + c]
    __shared__ float spen[CG];

    int tid = threadIdx.x;
    int grp = blockIdx.y;
    int cnt = min(g_count, CAND_CAP);
    if (cnt <= 0) return;

    const float4* qn4 = (const float4*)g_qn;
    const float4* K4  = (const float4*)Kbank;

    // ---- load 64 queries transposed: lane c = tid&63, quad-row d4 ----
    {
        int q = tid & 63, d4b = tid >> 6;
        int b = grp * QG + q;
        #pragma unroll
        for (int i = 0; i < 16; i++) {
            int d4 = d4b + 4 * i;
            float4 v = (b < B) ? qn4[(size_t)b * (DIM / 4) + d4]
                               : make_float4(0.f, 0.f, 0.f, 0.f);
            qs[(d4 * 4 + 0) * QG + q] = v.x;
            qs[(d4 * 4 + 1) * QG + q] = v.y;
            qs[(d4 * 4 + 2) * QG + q] = v.z;
            qs[(d4 * 4 + 3) * QG + q] = v.w;
        }
    }

    int cq = tid & 15, qq = tid >> 4;
    int c0 = cq * 4, q0 = qq * 4;

    for (int m0 = blockIdx.x * CG; m0 < cnt; m0 += gridDim.x * CG) {
        __syncthreads();   // protect kv/spen from previous iteration's readers

        // ---- load 64 candidate K rows transposed ----
        {
            int c = tid & 63, d4b = tid >> 6;
            int row = g_cidx[min(m0 + c, cnt - 1)];
            #pragma unroll
            for (int i = 0; i < 16; i++) {
                int d4 = d4b + 4 * i;
                float4 v = K4[(size_t)row * (DIM / 4) + d4];
                kv[(d4 * 4 + 0) * CG + c] = v.x;
                kv[(d4 * 4 + 1) * CG + c] = v.y;
                kv[(d4 * 4 + 2) * CG + c] = v.z;
                kv[(d4 * 4 + 3) * CG + c] = v.w;
            }
        }
        if (tid < CG) spen[tid] = g_cpen[min(m0 + tid, cnt - 1)];
        __syncthreads();

        // ---- 4x4 register-tile accumulation over d ----
        float acc[16];
        #pragma unroll
        for (int i = 0; i < 16; i++) acc[i] = 0.0f;

        #pragma unroll 4
        for (int d = 0; d < DIM; d++) {
            float4 kf = *(const float4*)&kv[d * CG + c0];
            float4 qf = *(const float4*)&qs[d * QG + q0];
            acc[0]  += qf.x * kf.x;  acc[1]  += qf.x * kf.y;
            acc[2]  += qf.x * kf.z;  acc[3]  += qf.x * kf.w;
            acc[4]  += qf.y * kf.x;  acc[5]  += qf.y * kf.y;
            acc[6]  += qf.y * kf.z;  acc[7]  += qf.y * kf.w;
            acc[8]  += qf.z * kf.x;  acc[9]  += qf.z * kf.y;
            acc[10] += qf.z * kf.z;  acc[11] += qf.z * kf.w;
            acc[12] += qf.w * kf.x;  acc[13] += qf.w * kf.y;
            acc[14] += qf.w * kf.z;  acc[15] += qf.w * kf.w;
        }

        // ---- store (float4 fast path, scalar tail) ----
        float p0 = spen[c0 + 0], p1 = spen[c0 + 1];
        float p2 = spen[c0 + 2], p3 = spen[c0 + 3];
        bool full = (m0 + c0 + 3) < cnt;
        #pragma unroll
        for (int qj = 0; qj < 4; qj++) {
            int b = grp * QG + q0 + qj;
            if (b >= B) break;
            float* dst = g_logits + (size_t)b * CAND_CAP + m0 + c0;
            float4 v;
            v.x = acc[qj * 4 + 0] * INV_TAU - p0;
            v.y = acc[qj * 4 + 1] * INV_TAU - p1;
            v.z = acc[qj * 4 + 2] * INV_TAU - p2;
            v.w = acc[qj * 4 + 3] * INV_TAU - p3;
            if (full) {
                *(float4*)dst = v;
            } else {
                float vv[4] = {v.x, v.y, v.z, v.w};
                for (int cj = 0; cj < 4; cj++)
                    if (m0 + c0 + cj < cnt) dst[cj] = vv[cj];
            }
        }
    }
}

// ---------------------------------------------------------------------------
// Kernel 6: per-query top-32 + softmax + V gather. Logit row cached in SMEM
// when it fits (usual case); gmem fallback otherwise.
// ---------------------------------------------------------------------------
__global__ void k_select(const float* __restrict__ Vbank,
                         float* __restrict__ out, int B) {
    __shared__ float srow[SROWCAP];
    __shared__ float rv[8];
    __shared__ int   ri[8];
    __shared__ float sv[TOPK];
    __shared__ int   si[TOPK];

    int b   = blockIdx.x;
    int tid = threadIdx.x;
    int cnt = min(g_count, CAND_CAP);
    float* grow = g_logits + (size_t)b * CAND_CAP;
    int lane = tid & 31, warp = tid >> 5;

    bool use_smem = (cnt <= SROWCAP);
    if (use_smem) {
        for (int m = tid; m < cnt; m += 256) srow[m] = grow[m];
        __syncthreads();
    }
    float* row = use_smem ? srow : grow;

    for (int k = 0; k < TOPK; k++) {
        float best = -FLT_MAX; int bidx = 0x7FFFFFFF;
        for (int m = tid; m < cnt; m += 256) {
            float v = row[m];
            if (v > best || (v == best && m < bidx)) { best = v; bidx = m; }
        }
        #pragma unroll
        for (int off = 16; off > 0; off >>= 1) {
            float ov = __shfl_down_sync(0xFFFFFFFFu, best, off);
            int   oi = __shfl_down_sync(0xFFFFFFFFu, bidx, off);
            if (ov > best || (ov == best && oi < bidx)) { best = ov; bidx = oi; }
        }
        if (lane == 0) { rv[warp] = best; ri[warp] = bidx; }
        __syncthreads();
        if (tid == 0) {
            float bb = rv[0]; int bi = ri[0];
            #pragma unroll
            for (int w = 1; w < 8; w++)
                if (rv[w] > bb || (rv[w] == bb && ri[w] < bi)) { bb = rv[w]; bi = ri[w]; }
            sv[k] = bb;
            si[k] = g_cidx[bi];
            row[bi] = -FLT_MAX;
        }
        __syncthreads();
    }

    // softmax over the 32 selected logits (warp 0)
    if (tid < 32) {
        float v = sv[tid];
        float mx = v;
        #pragma unroll
        for (int off = 16; off > 0; off >>= 1)
            mx = fmaxf(mx, __shfl_xor_sync(0xFFFFFFFFu, mx, off));
        float e = expf(v - mx);
        float s = e;
        #pragma unroll
        for (int off = 16; off > 0; off >>= 1)
            s += __shfl_xor_sync(0xFFFFFFFFu, s, off);
        sv[tid] = e / s;
    }
    __syncthreads();

    // gather: out[b, d] = sum_k attn[k] * V[idx_k, d]   (tid == d)
    float acc = 0.0f;
    #pragma unroll
    for (int k = 0; k < TOPK; k++)
        acc += sv[k] * Vbank[(size_t)si[k] * DIM + tid];
    out[b * DIM + tid] = acc;
}

// ---------------------------------------------------------------------------
extern "C" void kernel_launch(void* const* d_in, const int* in_sizes, int n_in,
                              void* d_out, int out_size) {
    const float* query = (const float*)d_in[0];
    const float* Kbank = (const float*)d_in[1];
    const float* Vbank = (const float*)d_in[2];
    const float* times = (const float*)d_in[3];
    const float* qtime = (const float*)d_in[4];
    float* out = (float*)d_out;

    int B = in_sizes[0] / DIM;
    int N = in_sizes[3];

    static int smem_set = 0;
    int logits_smem = (DIM * QG + DIM * CG) * (int)sizeof(float);  // 128 KB
    if (!smem_set) {
        cudaFuncSetAttribute(k_logits, cudaFuncAttributeMaxDynamicSharedMemorySize,
                             logits_smem);
        smem_set = 1;
    }

    k_init<<<1, 32>>>();
    k_minscan<<<128, 256>>>(times, qtime, N);
    k_fin<<<1, 32>>>();
    k_norm<<<B, DIM>>>(query, B);
    k_compact<<<(N + 255) / 256, 256>>>(times, qtime, N);
    dim3 g5(80, (B + QG - 1) / QG);
    k_logits<<<g5, 256, logits_smem>>>(Kbank, B);
    k_select<<<B, 256>>>(Vbank, out, B);
}

// round 3
// speedup vs baseline: 1.9580x; 1.2168x over previous
#include <cuda_runtime.h>
#include <float.h>
#include <math.h>

// Problem constants (shapes fixed by the dataset)
#define DIM       256
#define MAXB      128
#define TOPK      32
#define CAND_CAP  65536

#define INV_TAU   10.0f     // 1 / 0.1
#define PEN_COEF  0.25f     // BETA / (2*SIGMA^2) = 0.5 / 2
#define SIM_BOUND 10.0f     // max |q.K| / tau  (q, K unit-norm)

#define QG 32               // queries per logits block
#define CG 64               // candidates per logits chunk
#define PRE_BLOCKS 148      // <= SM count: all resident -> spin barrier is safe

// ---------------- scratch (device globals; no allocation allowed) ----------
__device__ unsigned int g_ctr;
__device__ int          g_count;
__device__ unsigned int g_gmin_bits[32];
__device__ int          g_cidx[CAND_CAP];
__device__ float        g_cpen[CAND_CAP];
__device__ float        g_qn[MAXB * DIM];
__device__ float        g_logits[(size_t)MAXB * CAND_CAP];   // 32 MB

// ---------------------------------------------------------------------------
// Kernel 0: reset barrier counter, candidate counter, per-residue minima.
// ---------------------------------------------------------------------------
__global__ void k_init() {
    if (threadIdx.x == 0) { g_count = 0; g_ctr = 0u; }
    if (threadIdx.x < 32) g_gmin_bits[threadIdx.x] = __float_as_uint(FLT_MAX);
}

// ---------------------------------------------------------------------------
// Kernel 1 (fused): query L2-norm + per-residue penalty minima + grid barrier
// + threshold + candidate compaction. Grid = PRE_BLOCKS (all resident).
//
// Threshold soundness: rows partitioned into 32 disjoint groups by (n mod 32);
// since gridDim*blockDim % 32 == 0, each thread's residue is fixed. The max
// over the 32 per-group minima is >= the 32nd-smallest penalty (32 distinct
// rows), so thresh = that + 2*SIM_BOUND + margin can never exclude a true
// top-32 row of any query. atomicMin on uint bits is order-preserving for
// non-negative floats.
// ---------------------------------------------------------------------------
__global__ void __launch_bounds__(256) k_pre(const float* __restrict__ times,
                                             const float* __restrict__ qtime,
                                             const float* __restrict__ query,
                                             int N, int B) {
    __shared__ float s[256];
    __shared__ float sth;
    int tid = threadIdx.x, bid = blockIdx.x;
    int nb = gridDim.x;

    // --- query L2 normalization (matches F.normalize, eps=1e-12) ---
    if (bid < B) {
        float v = query[bid * DIM + tid];
        s[tid] = v * v;
        __syncthreads();
        #pragma unroll
        for (int st = 128; st > 0; st >>= 1) {
            if (tid < st) s[tid] += s[tid + st];
            __syncthreads();
        }
        float nrm = fmaxf(sqrtf(s[0]), 1e-12f);
        __syncthreads();                   // everyone done reading s[0]
        g_qn[bid * DIM + tid] = v / nrm;
    }

    // --- per-residue-group penalty minima ---
    float qt = qtime[0];
    float lmin = FLT_MAX;
    int stride = nb * 256;                 // multiple of 32 -> residue fixed
    for (int n = bid * 256 + tid; n < N; n += stride) {
        float dt = qt - times[n];
        lmin = fminf(lmin, PEN_COEF * dt * dt);
    }
    s[tid] = lmin;
    __syncthreads();
    if (tid < 32) {
        float m = s[tid];
        #pragma unroll
        for (int w = 1; w < 8; w++) m = fminf(m, s[w * 32 + tid]);
        atomicMin(&g_gmin_bits[tid], __float_as_uint(m));
    }
    __syncthreads();

    // --- grid barrier (monotonic counter, reset by k_init each launch) ---
    if (tid == 0) {
        __threadfence();
        atomicAdd(&g_ctr, 1u);
        while (atomicAdd(&g_ctr, 0u) < (unsigned)nb) __nanosleep(32);
        __threadfence();
        float mx = -FLT_MAX;
        #pragma unroll
        for (int g = 0; g < 32; g++)
            mx = fmaxf(mx, __uint_as_float(g_gmin_bits[g]));
        sth = mx + 2.0f * SIM_BOUND + 4.0f;   // sound bound + fp margin
    }
    __syncthreads();
    float thresh = sth;

    // --- compact candidate rows ---
    for (int n = bid * 256 + tid; n < N; n += stride) {
        float dt = qt - times[n];
        float p = PEN_COEF * dt * dt;
        if (p <= thresh) {
            int pos = atomicAdd(&g_count, 1);
            if (pos < CAND_CAP) { g_cidx[pos] = n; g_cpen[pos] = p; }
        }
    }
}

// ---------------------------------------------------------------------------
// Kernel 2: exact fp32 logits, register-tiled.
// Block tile QG=32 queries x CG=64 candidates, 128 threads, 4x4 per-thread
// register tile. 96 KB dynamic SMEM -> 2 blocks/SM (fine work granularity,
// no second-wave cliff). Inner d-step: 2x LDS.128 + 16 FMA (ratio 2:1, FMA
// and SMEM-crossbar pipes balanced).
// ---------------------------------------------------------------------------
extern __shared__ float s_dyn[];   // qs[DIM*QG] then kv[DIM*CG]

__global__ void __launch_bounds__(128, 2)
k_logits(const float* __restrict__ Kbank, int B) {
    float* qs = s_dyn;             // [d*QG + q]
    float* kv = s_dyn + DIM * QG;  // [d*CG + c]
    __shared__ float spen[CG];

    int tid = threadIdx.x;
    int grp = blockIdx.y;
    int cnt = min(g_count, CAND_CAP);
    if (cnt <= 0) return;

    const float4* qn4 = (const float4*)g_qn;
    const float4* K4  = (const float4*)Kbank;

    // ---- load 32 queries transposed ----
    {
        int q = tid & 31, d4b = tid >> 5;          // d4b in 0..3
        int b = grp * QG + q;
        #pragma unroll
        for (int i = 0; i < 16; i++) {
            int d4 = d4b + 4 * i;
            float4 v = (b < B) ? qn4[(size_t)b * (DIM / 4) + d4]
                               : make_float4(0.f, 0.f, 0.f, 0.f);
            qs[(d4 * 4 + 0) * QG + q] = v.x;
            qs[(d4 * 4 + 1) * QG + q] = v.y;
            qs[(d4 * 4 + 2) * QG + q] = v.z;
            qs[(d4 * 4 + 3) * QG + q] = v.w;
        }
    }

    int cq = tid & 15, qq = tid >> 4;              // 16 x 8 thread grid
    int c0 = cq * 4, q0 = qq * 4;

    for (int m0 = blockIdx.x * CG; m0 < cnt; m0 += gridDim.x * CG) {
        __syncthreads();   // protect kv/spen from previous iteration's readers

        // ---- load 64 candidate K rows transposed ----
        {
            int c = tid & 63, d4b = tid >> 6;      // d4b in 0..1
            int row = g_cidx[min(m0 + c, cnt - 1)];
            #pragma unroll
            for (int i = 0; i < 32; i++) {
                int d4 = d4b + 2 * i;
                float4 v = K4[(size_t)row * (DIM / 4) + d4];
                kv[(d4 * 4 + 0) * CG + c] = v.x;
                kv[(d4 * 4 + 1) * CG + c] = v.y;
                kv[(d4 * 4 + 2) * CG + c] = v.z;
                kv[(d4 * 4 + 3) * CG + c] = v.w;
            }
        }
        if (tid < CG) spen[tid] = g_cpen[min(m0 + tid, cnt - 1)];
        __syncthreads();

        // ---- 4x4 register-tile accumulation over d ----
        float acc[16];
        #pragma unroll
        for (int i = 0; i < 16; i++) acc[i] = 0.0f;

        #pragma unroll 4
        for (int d = 0; d < DIM; d++) {
            float4 kf = *(const float4*)&kv[d * CG + c0];
            float4 qf = *(const float4*)&qs[d * QG + q0];
            acc[0]  += qf.x * kf.x;  acc[1]  += qf.x * kf.y;
            acc[2]  += qf.x * kf.z;  acc[3]  += qf.x * kf.w;
            acc[4]  += qf.y * kf.x;  acc[5]  += qf.y * kf.y;
            acc[6]  += qf.y * kf.z;  acc[7]  += qf.y * kf.w;
            acc[8]  += qf.z * kf.x;  acc[9]  += qf.z * kf.y;
            acc[10] += qf.z * kf.z;  acc[11] += qf.z * kf.w;
            acc[12] += qf.w * kf.x;  acc[13] += qf.w * kf.y;
            acc[14] += qf.w * kf.z;  acc[15] += qf.w * kf.w;
        }

        // ---- store (float4 fast path, scalar tail) ----
        float p0 = spen[c0 + 0], p1 = spen[c0 + 1];
        float p2 = spen[c0 + 2], p3 = spen[c0 + 3];
        bool full = (m0 + c0 + 3) < cnt;
        #pragma unroll
        for (int qj = 0; qj < 4; qj++) {
            int b = grp * QG + q0 + qj;
            if (b >= B) break;
            float* dst = g_logits + (size_t)b * CAND_CAP + m0 + c0;
            float4 v;
            v.x = acc[qj * 4 + 0] * INV_TAU - p0;
            v.y = acc[qj * 4 + 1] * INV_TAU - p1;
            v.z = acc[qj * 4 + 2] * INV_TAU - p2;
            v.w = acc[qj * 4 + 3] * INV_TAU - p3;
            if (full) {
                *(float4*)dst = v;
            } else {
                float vv[4] = {v.x, v.y, v.z, v.w};
                for (int cj = 0; cj < 4; cj++)
                    if (m0 + c0 + cj < cnt) dst[cj] = vv[cj];
            }
        }
    }
}

// ---------------------------------------------------------------------------
// Kernel 3: per-query top-32 + softmax + V gather.
// Fast path (cnt <= 8192): logit row lives in registers (32/thread); each
// warp builds its own sorted top-32 with shuffle-only argmax passes (no block
// barriers), then warp 0 merges the 8 sorted lists. Slow fallback otherwise.
// ---------------------------------------------------------------------------
__global__ void __launch_bounds__(256) k_select(const float* __restrict__ Vbank,
                                                float* __restrict__ out, int B) {
    __shared__ float wv[8 * TOPK];
    __shared__ int   wi[8 * TOPK];
    __shared__ float sv[TOPK];
    __shared__ int   si[TOPK];
    __shared__ float rv[8];
    __shared__ int   ri[8];

    int b = blockIdx.x, tid = threadIdx.x;
    int lane = tid & 31, warp = tid >> 5;
    int cnt = min(g_count, CAND_CAP);
    float* grow = g_logits + (size_t)b * CAND_CAP;

    if (cnt <= 8192) {
        // ---- registers: element m = tid + j*256 ----
        float lv[32];
        #pragma unroll
        for (int j = 0; j < 32; j++) {
            int m = tid + j * 256;
            lv[j] = (m < cnt) ? grow[m] : -FLT_MAX;
        }
        // ---- per-warp top-32 (sorted descending), shuffle-only ----
        for (int k = 0; k < TOPK; k++) {
            float best = -FLT_MAX; int bj = 0;
            #pragma unroll
            for (int j = 0; j < 32; j++)
                if (lv[j] > best) { best = lv[j]; bj = j; }   // keeps lowest j on tie
            int bm = (best > -FLT_MAX) ? (tid + (bj << 8)) : 0x7FFFFFFF;
            #pragma unroll
            for (int off = 16; off > 0; off >>= 1) {
                float ov = __shfl_down_sync(0xFFFFFFFFu, best, off);
                int   oi = __shfl_down_sync(0xFFFFFFFFu, bm, off);
                if (ov > best || (ov == best && oi < bm)) { best = ov; bm = oi; }
            }
            best = __shfl_sync(0xFFFFFFFFu, best, 0);
            bm   = __shfl_sync(0xFFFFFFFFu, bm, 0);
            if (lane == 0) { wv[warp * TOPK + k] = best; wi[warp * TOPK + k] = bm; }
            if (bm != 0x7FFFFFFF && (bm & 255) == tid) lv[bm >> 8] = -FLT_MAX;
        }
        __syncthreads();
        // ---- merge 8 sorted lists in warp 0 ----
        if (warp == 0) {
            int ptr = 0;                   // per-lane list pointer (lanes 0..7)
            for (int k = 0; k < TOPK; k++) {
                float hv = -FLT_MAX; int hm = 0x7FFFFFFF;
                if (lane < 8 && ptr < TOPK) {
                    hv = wv[lane * TOPK + ptr];
                    hm = wi[lane * TOPK + ptr];
                }
                float bestv = hv; int bestm = hm; int bl = lane;
                #pragma unroll
                for (int off = 16; off > 0; off >>= 1) {
                    float ov = __shfl_down_sync(0xFFFFFFFFu, bestv, off);
                    int   oi = __shfl_down_sync(0xFFFFFFFFu, bestm, off);
                    int   ol = __shfl_down_sync(0xFFFFFFFFu, bl, off);
                    if (ov > bestv || (ov == bestv && oi < bestm)) {
                        bestv = ov; bestm = oi; bl = ol;
                    }
                }
                bestv = __shfl_sync(0xFFFFFFFFu, bestv, 0);
                bestm = __shfl_sync(0xFFFFFFFFu, bestm, 0);
                bl    = __shfl_sync(0xFFFFFFFFu, bl, 0);
                if (lane == 0) { sv[k] = bestv; si[k] = bestm; }
                if (lane == bl) ptr++;
            }
        }
    } else {
        // ---- fallback: iterative argmax over gmem row (never expected) ----
        for (int k = 0; k < TOPK; k++) {
            float best = -FLT_MAX; int bidx = 0x7FFFFFFF;
            for (int m = tid; m < cnt; m += 256) {
                float v = grow[m];
                if (v > best || (v == best && m < bidx)) { best = v; bidx = m; }
            }
            #pragma unroll
            for (int off = 16; off > 0; off >>= 1) {
                float ov = __shfl_down_sync(0xFFFFFFFFu, best, off);
                int   oi = __shfl_down_sync(0xFFFFFFFFu, bidx, off);
                if (ov > best || (ov == best && oi < bidx)) { best = ov; bidx = oi; }
            }
            if (lane == 0) { rv[warp] = best; ri[warp] = bidx; }
            __syncthreads();
            if (tid == 0) {
                float bb = rv[0]; int bi = ri[0];
                #pragma unroll
                for (int w = 1; w < 8; w++)
                    if (rv[w] > bb || (rv[w] == bb && ri[w] < bi)) { bb = rv[w]; bi = ri[w]; }
                sv[k] = bb; si[k] = bi; grow[bi] = -FLT_MAX;
            }
            __syncthreads();
        }
    }
    __syncthreads();

    // ---- map candidate position -> original row index ----
    if (tid < TOPK) si[tid] = g_cidx[min(si[tid], cnt - 1)];
    __syncthreads();

    // ---- softmax over the 32 selected logits (warp 0) ----
    if (tid < 32) {
        float v = sv[tid];
        float mx = v;
        #pragma unroll
        for (int off = 16; off > 0; off >>= 1)
            mx = fmaxf(mx, __shfl_xor_sync(0xFFFFFFFFu, mx, off));
        float e = expf(v - mx);
        float ssum = e;
        #pragma unroll
        for (int off = 16; off > 0; off >>= 1)
            ssum += __shfl_xor_sync(0xFFFFFFFFu, ssum, off);
        sv[tid] = e / ssum;
    }
    __syncthreads();

    // ---- gather: out[b, d] = sum_k attn[k] * V[idx_k, d]   (tid == d) ----
    float acc = 0.0f;
    #pragma unroll
    for (int k = 0; k < TOPK; k++)
        acc += sv[k] * Vbank[(size_t)si[k] * DIM + tid];
    out[b * DIM + tid] = acc;
}

// ---------------------------------------------------------------------------
extern "C" void kernel_launch(void* const* d_in, const int* in_sizes, int n_in,
                              void* d_out, int out_size) {
    const float* query = (const float*)d_in[0];
    const float* Kbank = (const float*)d_in[1];
    const float* Vbank = (const float*)d_in[2];
    const float* times = (const float*)d_in[3];
    const float* qtime = (const float*)d_in[4];
    float* out = (float*)d_out;

    int B = in_sizes[0] / DIM;
    int N = in_sizes[3];

    int logits_smem = (DIM * QG + DIM * CG) * (int)sizeof(float);  // 96 KB
    cudaFuncSetAttribute(k_logits, cudaFuncAttributeMaxDynamicSharedMemorySize,
                         logits_smem);

    k_init<<<1, 32>>>();
    k_pre<<<PRE_BLOCKS, 256>>>(times, qtime, query, N, B);
    dim3 g3(80, (B + QG - 1) / QG);
    k_logits<<<g3, 128, logits_smem>>>(Kbank, B);
    k_select<<<B, 256>>>(Vbank, out, B);
}

// round 4
// speedup vs baseline: 2.0934x; 1.0692x over previous
#include <cuda_runtime.h>
#include <float.h>
#include <math.h>

// Problem constants (shapes fixed by the dataset)
#define DIM       256
#define MAXB      128
#define TOPK      32
#define CAND_CAP  65536

#define INV_TAU   10.0f     // 1 / 0.1
#define PEN_COEF  0.25f     // BETA / (2*SIGMA^2) = 0.5 / 2
#define SIM_BOUND 10.0f     // max |q.K| / tau  (q, K unit-norm)

#define QG 32               // queries per logits block
#define CG 64               // candidates per logits chunk
#define PRE_BLOCKS 148      // <= SM count: all resident -> spin barrier is safe
#define CAP2 2048           // filtered-candidate capacity in k_select

// ---------------- scratch (device globals; no allocation allowed) ----------
__device__ unsigned int g_ctr;
__device__ int          g_count;
__device__ unsigned int g_gmin_bits[32];
__device__ int          g_cidx[CAND_CAP];
__device__ float        g_cpen[CAND_CAP];
__device__ float        g_qn[MAXB * DIM];
__device__ float        g_logits[(size_t)MAXB * CAND_CAP];   // 32 MB

// order-preserving float -> uint (descending float == descending uint)
__device__ __forceinline__ unsigned int f2u_ord(float f) {
    unsigned int u = __float_as_uint(f);
    return (u & 0x80000000u) ? ~u : (u | 0x80000000u);
}

// ---------------------------------------------------------------------------
// Kernel 0: reset barrier counter, candidate counter, per-residue minima.
// ---------------------------------------------------------------------------
__global__ void k_init() {
    if (threadIdx.x == 0) { g_count = 0; g_ctr = 0u; }
    if (threadIdx.x < 32) g_gmin_bits[threadIdx.x] = __float_as_uint(FLT_MAX);
}

// ---------------------------------------------------------------------------
// Kernel 1 (fused): query L2-norm + per-residue penalty minima + grid barrier
// + threshold + candidate compaction. Grid = PRE_BLOCKS (all resident).
// Threshold soundness: rows partitioned into 32 disjoint groups by (n mod 32);
// max over the 32 per-group minima >= 32nd-smallest penalty, so
// thresh = bound + 2*SIM_BOUND + margin can never drop a true top-32 row.
// ---------------------------------------------------------------------------
__global__ void __launch_bounds__(256) k_pre(const float* __restrict__ times,
                                             const float* __restrict__ qtime,
                                             const float* __restrict__ query,
                                             int N, int B) {
    __shared__ float s[256];
    __shared__ float sth;
    int tid = threadIdx.x, bid = blockIdx.x;
    int nb = gridDim.x;

    // --- query L2 normalization (matches F.normalize, eps=1e-12) ---
    if (bid < B) {
        float v = query[bid * DIM + tid];
        s[tid] = v * v;
        __syncthreads();
        #pragma unroll
        for (int st = 128; st > 0; st >>= 1) {
            if (tid < st) s[tid] += s[tid + st];
            __syncthreads();
        }
        float nrm = fmaxf(sqrtf(s[0]), 1e-12f);
        __syncthreads();
        g_qn[bid * DIM + tid] = v / nrm;
    }

    // --- per-residue-group penalty minima ---
    float qt = qtime[0];
    float lmin = FLT_MAX;
    int stride = nb * 256;                 // multiple of 32 -> residue fixed
    for (int n = bid * 256 + tid; n < N; n += stride) {
        float dt = qt - times[n];
        lmin = fminf(lmin, PEN_COEF * dt * dt);
    }
    s[tid] = lmin;
    __syncthreads();
    if (tid < 32) {
        float m = s[tid];
        #pragma unroll
        for (int w = 1; w < 8; w++) m = fminf(m, s[w * 32 + tid]);
        atomicMin(&g_gmin_bits[tid], __float_as_uint(m));
    }
    __syncthreads();

    // --- grid barrier (counter reset by k_init each launch) ---
    if (tid == 0) {
        __threadfence();
        atomicAdd(&g_ctr, 1u);
        while (atomicAdd(&g_ctr, 0u) < (unsigned)nb) __nanosleep(32);
        __threadfence();
        float mx = -FLT_MAX;
        #pragma unroll
        for (int g = 0; g < 32; g++)
            mx = fmaxf(mx, __uint_as_float(g_gmin_bits[g]));
        sth = mx + 2.0f * SIM_BOUND + 4.0f;   // sound bound + fp margin
    }
    __syncthreads();
    float thresh = sth;

    // --- compact candidate rows ---
    for (int n = bid * 256 + tid; n < N; n += stride) {
        float dt = qt - times[n];
        float p = PEN_COEF * dt * dt;
        if (p <= thresh) {
            int pos = atomicAdd(&g_count, 1);
            if (pos < CAND_CAP) { g_cidx[pos] = n; g_cpen[pos] = p; }
        }
    }
}

// ---------------------------------------------------------------------------
// Kernel 2: exact fp32 logits, register-tiled.
// Block tile QG=32 x CG=64, 128 threads, 4x4 register tile, 96 KB SMEM,
// 2 blocks/SM. Inner d-step: 2x LDS.128 + 16 FMA.
// ---------------------------------------------------------------------------
extern __shared__ float s_dyn[];   // qs[DIM*QG] then kv[DIM*CG]

__global__ void __launch_bounds__(128, 2)
k_logits(const float* __restrict__ Kbank, int B) {
    float* qs = s_dyn;             // [d*QG + q]
    float* kv = s_dyn + DIM * QG;  // [d*CG + c]
    __shared__ float spen[CG];

    int tid = threadIdx.x;
    int grp = blockIdx.y;
    int cnt = min(g_count, CAND_CAP);
    if (cnt <= 0) return;

    const float4* qn4 = (const float4*)g_qn;
    const float4* K4  = (const float4*)Kbank;

    // ---- load 32 queries transposed ----
    {
        int q = tid & 31, d4b = tid >> 5;
        int b = grp * QG + q;
        #pragma unroll
        for (int i = 0; i < 16; i++) {
            int d4 = d4b + 4 * i;
            float4 v = (b < B) ? qn4[(size_t)b * (DIM / 4) + d4]
                               : make_float4(0.f, 0.f, 0.f, 0.f);
            qs[(d4 * 4 + 0) * QG + q] = v.x;
            qs[(d4 * 4 + 1) * QG + q] = v.y;
            qs[(d4 * 4 + 2) * QG + q] = v.z;
            qs[(d4 * 4 + 3) * QG + q] = v.w;
        }
    }

    int cq = tid & 15, qq = tid >> 4;
    int c0 = cq * 4, q0 = qq * 4;

    for (int m0 = blockIdx.x * CG; m0 < cnt; m0 += gridDim.x * CG) {
        __syncthreads();

        // ---- load 64 candidate K rows transposed ----
        {
            int c = tid & 63, d4b = tid >> 6;
            int row = g_cidx[min(m0 + c, cnt - 1)];
            #pragma unroll
            for (int i = 0; i < 32; i++) {
                int d4 = d4b + 2 * i;
                float4 v = K4[(size_t)row * (DIM / 4) + d4];
                kv[(d4 * 4 + 0) * CG + c] = v.x;
                kv[(d4 * 4 + 1) * CG + c] = v.y;
                kv[(d4 * 4 + 2) * CG + c] = v.z;
                kv[(d4 * 4 + 3) * CG + c] = v.w;
            }
        }
        if (tid < CG) spen[tid] = g_cpen[min(m0 + tid, cnt - 1)];
        __syncthreads();

        float acc[16];
        #pragma unroll
        for (int i = 0; i < 16; i++) acc[i] = 0.0f;

        #pragma unroll 4
        for (int d = 0; d < DIM; d++) {
            float4 kf = *(const float4*)&kv[d * CG + c0];
            float4 qf = *(const float4*)&qs[d * QG + q0];
            acc[0]  += qf.x * kf.x;  acc[1]  += qf.x * kf.y;
            acc[2]  += qf.x * kf.z;  acc[3]  += qf.x * kf.w;
            acc[4]  += qf.y * kf.x;  acc[5]  += qf.y * kf.y;
            acc[6]  += qf.y * kf.z;  acc[7]  += qf.y * kf.w;
            acc[8]  += qf.z * kf.x;  acc[9]  += qf.z * kf.y;
            acc[10] += qf.z * kf.z;  acc[11] += qf.z * kf.w;
            acc[12] += qf.w * kf.x;  acc[13] += qf.w * kf.y;
            acc[14] += qf.w * kf.z;  acc[15] += qf.w * kf.w;
        }

        float p0 = spen[c0 + 0], p1 = spen[c0 + 1];
        float p2 = spen[c0 + 2], p3 = spen[c0 + 3];
        bool full = (m0 + c0 + 3) < cnt;
        #pragma unroll
        for (int qj = 0; qj < 4; qj++) {
            int b = grp * QG + q0 + qj;
            if (b >= B) break;
            float* dst = g_logits + (size_t)b * CAND_CAP + m0 + c0;
            float4 v;
            v.x = acc[qj * 4 + 0] * INV_TAU - p0;
            v.y = acc[qj * 4 + 1] * INV_TAU - p1;
            v.z = acc[qj * 4 + 2] * INV_TAU - p2;
            v.w = acc[qj * 4 + 3] * INV_TAU - p3;
            if (full) {
                *(float4*)dst = v;
            } else {
                float vv[4] = {v.x, v.y, v.z, v.w};
                for (int cj = 0; cj < 4; cj++)
                    if (m0 + c0 + cj < cnt) dst[cj] = vv[cj];
            }
        }
    }
}

// ---------------------------------------------------------------------------
// Kernel 3: per-query top-32 via radix-histogram filter + exact extraction,
// then softmax + V gather. One block (256 thr) per query.
//
// Filter: 256-bin histogram of the top byte of the order-preserving uint,
// suffix-sum, threshold bin t = largest bin with suffix >= 32. Elements in
// bins >= t are a superset of the top-32. Collected set (typ. << CAP2) then
// goes through per-warp sorted extraction + 8-way merge. Fallback to full
// iterative argmax if the filter overflows CAP2.
// ---------------------------------------------------------------------------
__global__ void __launch_bounds__(256) k_select(const float* __restrict__ Vbank,
                                                float* __restrict__ out, int B) {
    __shared__ unsigned int sa[256], sb[256];
    __shared__ float cv[CAP2];
    __shared__ int   ci[CAP2];
    __shared__ int   s_t, s_n;
    __shared__ float wv[8 * TOPK];
    __shared__ int   wi[8 * TOPK];
    __shared__ float sv[TOPK];
    __shared__ int   si[TOPK];
    __shared__ float rv[8];
    __shared__ int   ri[8];

    int b = blockIdx.x, tid = threadIdx.x;
    int lane = tid & 31, warp = tid >> 5;
    int cnt = min(g_count, CAND_CAP);
    float* grow = g_logits + (size_t)b * CAND_CAP;

    // ---- pass 1: histogram of top byte ----
    sa[tid] = 0u;
    if (tid == 0) s_n = 0;
    __syncthreads();
    for (int m = tid; m < cnt; m += 256)
        atomicAdd(&sa[f2u_ord(grow[m]) >> 24], 1u);
    __syncthreads();

    // ---- suffix sum over 256 bins (Hillis-Steele, ping-pong) ----
    unsigned int* src = sa; unsigned int* dst = sb;
    #pragma unroll
    for (int off = 1; off < 256; off <<= 1) {
        dst[tid] = src[tid] + ((tid + off < 256) ? src[tid + off] : 0u);
        __syncthreads();
        unsigned int* tmp = src; src = dst; dst = tmp;
    }
    // src[tid] = count of elements with bin >= tid
    if (tid == 0 && src[0] < TOPK) s_t = 0;                 // take everything
    unsigned int nxt = (tid < 255) ? src[tid + 1] : 0u;
    if (src[tid] >= TOPK && nxt < TOPK) s_t = tid;          // unique
    __syncthreads();
    int tbin = s_t;

    // ---- pass 2: collect elements with bin >= tbin ----
    for (int m = tid; m < cnt; m += 256) {
        float v = grow[m];
        if ((int)(f2u_ord(v) >> 24) >= tbin) {
            int pos = atomicAdd(&s_n, 1);
            if (pos < CAP2) { cv[pos] = v; ci[pos] = m; }
        }
    }
    __syncthreads();
    int ncand = s_n;

    if (ncand <= CAP2) {
        // ---- per-warp sorted top-32 over the filtered set ----
        float lv[CAP2 / 256];
        int   li[CAP2 / 256];
        #pragma unroll
        for (int j = 0; j < CAP2 / 256; j++) {
            int slot = tid + j * 256;
            bool ok = slot < ncand;
            lv[j] = ok ? cv[slot] : -FLT_MAX;
            li[j] = ok ? ci[slot] : 0x7FFFFFFF;
        }
        for (int k = 0; k < TOPK; k++) {
            float best = -FLT_MAX; int bj = 0, bidx = 0x7FFFFFFF;
            #pragma unroll
            for (int j = 0; j < CAP2 / 256; j++)
                if (lv[j] > best || (lv[j] == best && li[j] < bidx)) {
                    best = lv[j]; bidx = li[j]; bj = j;
                }
            int benc = (bj << 8) | tid;       // winner's reg+lane
            #pragma unroll
            for (int off = 16; off > 0; off >>= 1) {
                float ov = __shfl_down_sync(0xFFFFFFFFu, best, off);
                int   oi = __shfl_down_sync(0xFFFFFFFFu, bidx, off);
                int   oe = __shfl_down_sync(0xFFFFFFFFu, benc, off);
                if (ov > best || (ov == best && oi < bidx)) {
                    best = ov; bidx = oi; benc = oe;
                }
            }
            best = __shfl_sync(0xFFFFFFFFu, best, 0);
            bidx = __shfl_sync(0xFFFFFFFFu, bidx, 0);
            benc = __shfl_sync(0xFFFFFFFFu, benc, 0);
            if (lane == 0) {
                wv[warp * TOPK + k] = best;
                wi[warp * TOPK + k] = bidx;
            }
            if ((benc & 255) == tid && best > -FLT_MAX) lv[benc >> 8] = -FLT_MAX;
        }
        __syncthreads();
        // ---- merge 8 sorted lists in warp 0 ----
        if (warp == 0) {
            int ptr = 0;
            for (int k = 0; k < TOPK; k++) {
                float hv = -FLT_MAX; int hm = 0x7FFFFFFF;
                if (lane < 8 && ptr < TOPK) {
                    hv = wv[lane * TOPK + ptr];
                    hm = wi[lane * TOPK + ptr];
                }
                float bestv = hv; int bestm = hm; int bl = lane;
                #pragma unroll
                for (int off = 16; off > 0; off >>= 1) {
                    float ov = __shfl_down_sync(0xFFFFFFFFu, bestv, off);
                    int   oi = __shfl_down_sync(0xFFFFFFFFu, bestm, off);
                    int   ol = __shfl_down_sync(0xFFFFFFFFu, bl, off);
                    if (ov > bestv || (ov == bestv && oi < bestm)) {
                        bestv = ov; bestm = oi; bl = ol;
                    }
                }
                bestv = __shfl_sync(0xFFFFFFFFu, bestv, 0);
                bestm = __shfl_sync(0xFFFFFFFFu, bestm, 0);
                bl    = __shfl_sync(0xFFFFFFFFu, bl, 0);
                if (lane == 0) { sv[k] = bestv; si[k] = bestm; }
                if (lane == bl) ptr++;
            }
        }
    } else {
        // ---- fallback: exact iterative argmax over gmem row ----
        for (int k = 0; k < TOPK; k++) {
            float best = -FLT_MAX; int bidx = 0x7FFFFFFF;
            for (int m = tid; m < cnt; m += 256) {
                float v = grow[m];
                if (v > best || (v == best && m < bidx)) { best = v; bidx = m; }
            }
            #pragma unroll
            for (int off = 16; off > 0; off >>= 1) {
                float ov = __shfl_down_sync(0xFFFFFFFFu, best, off);
                int   oi = __shfl_down_sync(0xFFFFFFFFu, bidx, off);
                if (ov > best || (ov == best && oi < bidx)) { best = ov; bidx = oi; }
            }
            if (lane == 0) { rv[warp] = best; ri[warp] = bidx; }
            __syncthreads();
            if (tid == 0) {
                float bb = rv[0]; int bi = ri[0];
                #pragma unroll
                for (int w = 1; w < 8; w++)
                    if (rv[w] > bb || (rv[w] == bb && ri[w] < bi)) { bb = rv[w]; bi = ri[w]; }
                sv[k] = bb; si[k] = bi; grow[bi] = -FLT_MAX;
            }
            __syncthreads();
        }
    }
    __syncthreads();

    // ---- map candidate position -> original row index ----
    if (tid < TOPK) si[tid] = g_cidx[min(si[tid], cnt - 1)];
    __syncthreads();

    // ---- softmax over the 32 selected logits (warp 0) ----
    if (tid < 32) {
        float v = sv[tid];
        float mx = v;
        #pragma unroll
        for (int off = 16; off > 0; off >>= 1)
            mx = fmaxf(mx, __shfl_xor_sync(0xFFFFFFFFu, mx, off));
        float e = expf(v - mx);
        float ssum = e;
        #pragma unroll
        for (int off = 16; off > 0; off >>= 1)
            ssum += __shfl_xor_sync(0xFFFFFFFFu, ssum, off);
        sv[tid] = e / ssum;
    }
    __syncthreads();

    // ---- gather: out[b, d] = sum_k attn[k] * V[idx_k, d]   (tid == d) ----
    float acc = 0.0f;
    #pragma unroll
    for (int k = 0; k < TOPK; k++)
        acc += sv[k] * Vbank[(size_t)si[k] * DIM + tid];
    out[b * DIM + tid] = acc;
}

// ---------------------------------------------------------------------------
extern "C" void kernel_launch(void* const* d_in, const int* in_sizes, int n_in,
                              void* d_out, int out_size) {
    const float* query = (const float*)d_in[0];
    const float* Kbank = (const float*)d_in[1];
    const float* Vbank = (const float*)d_in[2];
    const float* times = (const float*)d_in[3];
    const float* qtime = (const float*)d_in[4];
    float* out = (float*)d_out;

    int B = in_sizes[0] / DIM;
    int N = in_sizes[3];

    int logits_smem = (DIM * QG + DIM * CG) * (int)sizeof(float);  // 96 KB
    cudaFuncSetAttribute(k_logits, cudaFuncAttributeMaxDynamicSharedMemorySize,
                         logits_smem);

    k_init<<<1, 32>>>();
    k_pre<<<PRE_BLOCKS, 256>>>(times, qtime, query, N, B);
    dim3 g3(74, (B + QG - 1) / QG);       // 296 blocks = 2/SM exactly
    k_logits<<<g3, 128, logits_smem>>>(Kbank, B);
    k_select<<<B, 256>>>(Vbank, out, B);
}

// round 5
// speedup vs baseline: 2.4037x; 1.1482x over previous
#include <cuda_runtime.h>
#include <float.h>
#include <math.h>

// Problem constants (shapes fixed by the dataset)
#define DIM       256
#define MAXB      128
#define TOPK      32
#define CAND_CAP  65536

#define INV_TAU   10.0f     // 1 / 0.1
#define PEN_COEF  0.25f     // BETA / (2*SIGMA^2) = 0.5 / 2
#define SIM_BOUND 10.0f     // max |q.K| / tau  (q, K unit-norm)

#define QG 32               // queries per logits block
#define CG 64               // candidates per logits chunk
#define PRE_BLOCKS 148      // <= SM count: all resident -> spin barrier is safe
#define CAP2 2048           // equal-prefix list capacity in k_select

// ---------------- scratch (device globals; no allocation allowed) ----------
__device__ unsigned int g_ctr;
__device__ int          g_count;
__device__ unsigned int g_gmin_bits[32];
__device__ int          g_cidx[CAND_CAP];
__device__ float        g_cpen[CAND_CAP];
__device__ float        g_qn[MAXB * DIM];
__device__ float        g_logits[(size_t)MAXB * CAND_CAP];   // 32 MB

// order-preserving float <-> uint (descending float == descending uint)
__device__ __forceinline__ unsigned int f2u_ord(float f) {
    unsigned int u = __float_as_uint(f);
    return (u & 0x80000000u) ? ~u : (u | 0x80000000u);
}
__device__ __forceinline__ float u2f_ord(unsigned int u) {
    return (u & 0x80000000u) ? __uint_as_float(u & 0x7FFFFFFFu)
                             : __uint_as_float(~u);
}

// ---------------------------------------------------------------------------
// Kernel 0: reset barrier counter, candidate counter, per-residue minima.
// ---------------------------------------------------------------------------
__global__ void k_init() {
    if (threadIdx.x == 0) { g_count = 0; g_ctr = 0u; }
    if (threadIdx.x < 32) g_gmin_bits[threadIdx.x] = __float_as_uint(FLT_MAX);
}

// ---------------------------------------------------------------------------
// Kernel 1 (fused): query L2-norm + per-residue penalty minima + grid barrier
// + threshold + candidate compaction. Grid = PRE_BLOCKS (all resident).
// Threshold soundness: rows partitioned into 32 disjoint groups by (n mod 32);
// max over the 32 per-group minima >= 32nd-smallest penalty, so
// thresh = bound + 2*SIM_BOUND + margin can never drop a true top-32 row.
// ---------------------------------------------------------------------------
__global__ void __launch_bounds__(256) k_pre(const float* __restrict__ times,
                                             const float* __restrict__ qtime,
                                             const float* __restrict__ query,
                                             int N, int B) {
    __shared__ float s[256];
    __shared__ float sth;
    int tid = threadIdx.x, bid = blockIdx.x;
    int nb = gridDim.x;

    // --- query L2 normalization (matches F.normalize, eps=1e-12) ---
    if (bid < B) {
        float v = query[bid * DIM + tid];
        s[tid] = v * v;
        __syncthreads();
        #pragma unroll
        for (int st = 128; st > 0; st >>= 1) {
            if (tid < st) s[tid] += s[tid + st];
            __syncthreads();
        }
        float nrm = fmaxf(sqrtf(s[0]), 1e-12f);
        __syncthreads();
        g_qn[bid * DIM + tid] = v / nrm;
    }

    // --- per-residue-group penalty minima ---
    float qt = qtime[0];
    float lmin = FLT_MAX;
    int stride = nb * 256;                 // multiple of 32 -> residue fixed
    for (int n = bid * 256 + tid; n < N; n += stride) {
        float dt = qt - times[n];
        lmin = fminf(lmin, PEN_COEF * dt * dt);
    }
    s[tid] = lmin;
    __syncthreads();
    if (tid < 32) {
        float m = s[tid];
        #pragma unroll
        for (int w = 1; w < 8; w++) m = fminf(m, s[w * 32 + tid]);
        atomicMin(&g_gmin_bits[tid], __float_as_uint(m));
    }
    __syncthreads();

    // --- grid barrier (counter reset by k_init each launch) ---
    if (tid == 0) {
        __threadfence();
        atomicAdd(&g_ctr, 1u);
        while (atomicAdd(&g_ctr, 0u) < (unsigned)nb) __nanosleep(32);
        __threadfence();
        float mx = -FLT_MAX;
        #pragma unroll
        for (int g = 0; g < 32; g++)
            mx = fmaxf(mx, __uint_as_float(g_gmin_bits[g]));
        sth = mx + 2.0f * SIM_BOUND + 4.0f;   // sound bound + fp margin
    }
    __syncthreads();
    float thresh = sth;

    // --- compact candidate rows ---
    for (int n = bid * 256 + tid; n < N; n += stride) {
        float dt = qt - times[n];
        float p = PEN_COEF * dt * dt;
        if (p <= thresh) {
            int pos = atomicAdd(&g_count, 1);
            if (pos < CAND_CAP) { g_cidx[pos] = n; g_cpen[pos] = p; }
        }
    }
}

// ---------------------------------------------------------------------------
// Kernel 2: exact fp32 logits, register-tiled.
// Block tile QG=32 x CG=64, 128 threads, 4x4 register tile, 96 KB SMEM,
// 2 blocks/SM. Inner d-step: 2x LDS.128 + 16 FMA.
// ---------------------------------------------------------------------------
extern __shared__ float s_dyn[];   // qs[DIM*QG] then kv[DIM*CG]

__global__ void __launch_bounds__(128, 2)
k_logits(const float* __restrict__ Kbank, int B) {
    float* qs = s_dyn;             // [d*QG + q]
    float* kv = s_dyn + DIM * QG;  // [d*CG + c]
    __shared__ float spen[CG];

    int tid = threadIdx.x;
    int grp = blockIdx.y;
    int cnt = min(g_count, CAND_CAP);
    if (cnt <= 0) return;

    const float4* qn4 = (const float4*)g_qn;
    const float4* K4  = (const float4*)Kbank;

    // ---- load 32 queries transposed ----
    {
        int q = tid & 31, d4b = tid >> 5;
        int b = grp * QG + q;
        #pragma unroll
        for (int i = 0; i < 16; i++) {
            int d4 = d4b + 4 * i;
            float4 v = (b < B) ? qn4[(size_t)b * (DIM / 4) + d4]
                               : make_float4(0.f, 0.f, 0.f, 0.f);
            qs[(d4 * 4 + 0) * QG + q] = v.x;
            qs[(d4 * 4 + 1) * QG + q] = v.y;
            qs[(d4 * 4 + 2) * QG + q] = v.z;
            qs[(d4 * 4 + 3) * QG + q] = v.w;
        }
    }

    int cq = tid & 15, qq = tid >> 4;
    int c0 = cq * 4, q0 = qq * 4;

    for (int m0 = blockIdx.x * CG; m0 < cnt; m0 += gridDim.x * CG) {
        __syncthreads();

        // ---- load 64 candidate K rows transposed ----
        {
            int c = tid & 63, d4b = tid >> 6;
            int row = g_cidx[min(m0 + c, cnt - 1)];
            #pragma unroll
            for (int i = 0; i < 32; i++) {
                int d4 = d4b + 2 * i;
                float4 v = K4[(size_t)row * (DIM / 4) + d4];
                kv[(d4 * 4 + 0) * CG + c] = v.x;
                kv[(d4 * 4 + 1) * CG + c] = v.y;
                kv[(d4 * 4 + 2) * CG + c] = v.z;
                kv[(d4 * 4 + 3) * CG + c] = v.w;
            }
        }
        if (tid < CG) spen[tid] = g_cpen[min(m0 + tid, cnt - 1)];
        __syncthreads();

        float acc[16];
        #pragma unroll
        for (int i = 0; i < 16; i++) acc[i] = 0.0f;

        #pragma unroll 4
        for (int d = 0; d < DIM; d++) {
            float4 kf = *(const float4*)&kv[d * CG + c0];
            float4 qf = *(const float4*)&qs[d * QG + q0];
            acc[0]  += qf.x * kf.x;  acc[1]  += qf.x * kf.y;
            acc[2]  += qf.x * kf.z;  acc[3]  += qf.x * kf.w;
            acc[4]  += qf.y * kf.x;  acc[5]  += qf.y * kf.y;
            acc[6]  += qf.y * kf.z;  acc[7]  += qf.y * kf.w;
            acc[8]  += qf.z * kf.x;  acc[9]  += qf.z * kf.y;
            acc[10] += qf.z * kf.z;  acc[11] += qf.z * kf.w;
            acc[12] += qf.w * kf.x;  acc[13] += qf.w * kf.y;
            acc[14] += qf.w * kf.z;  acc[15] += qf.w * kf.w;
        }

        float p0 = spen[c0 + 0], p1 = spen[c0 + 1];
        float p2 = spen[c0 + 2], p3 = spen[c0 + 3];
        bool full = (m0 + c0 + 3) < cnt;
        #pragma unroll
        for (int qj = 0; qj < 4; qj++) {
            int b = grp * QG + q0 + qj;
            if (b >= B) break;
            float* dst = g_logits + (size_t)b * CAND_CAP + m0 + c0;
            float4 v;
            v.x = acc[qj * 4 + 0] * INV_TAU - p0;
            v.y = acc[qj * 4 + 1] * INV_TAU - p1;
            v.z = acc[qj * 4 + 2] * INV_TAU - p2;
            v.w = acc[qj * 4 + 3] * INV_TAU - p3;
            if (full) {
                *(float4*)dst = v;
            } else {
                float vv[4] = {v.x, v.y, v.z, v.w};
                for (int cj = 0; cj < 4; cj++)
                    if (m0 + c0 + cj < cnt) dst[cj] = vv[cj];
            }
        }
    }
}

// ---------------------------------------------------------------------------
// Kernel 3: per-query EXACT top-32 via 4-level radix select (no sorting —
// the attention sum is permutation-invariant, only the SET matters), then
// softmax + V gather. One block (256 thr) per query.
//
// Level l examines byte (3-l) of the order-preserving uint. Elements with a
// strictly greater byte than the cutoff bin are winners; elements equal to
// the bin recurse on the next byte over a shrinking SMEM list. Exact ties
// at byte 0 are resolved by lowest candidate index (== jax top_k order).
// Histogram atomics are warp-aggregated via __match_any_sync.
// ---------------------------------------------------------------------------
__global__ void __launch_bounds__(256) k_select(const float* __restrict__ Vbank,
                                                float* __restrict__ out, int B) {
    __shared__ unsigned int h0[256], h1[256];
    __shared__ unsigned int equ[2][CAP2];
    __shared__ int          eqi[2][CAP2];
    __shared__ float winv[TOPK];
    __shared__ int   wini[TOPK];
    __shared__ int   s_nwin, s_neq[2], s_b;
    __shared__ float rv[8];
    __shared__ int   ri[8];

    int b = blockIdx.x, tid = threadIdx.x;
    int lane = tid & 31, warp = tid >> 5;
    int cnt = min(g_count, CAND_CAP);
    float* grow = g_logits + (size_t)b * CAND_CAP;

    if (tid == 0) { s_nwin = 0; s_neq[0] = 0; s_neq[1] = 0; }
    h0[tid] = 0u;
    __syncthreads();

    // ---- level 0: histogram of top byte (gmem pass, warp-aggregated) ----
    for (int m = tid; m < cnt; m += 256) {
        unsigned int bin = f2u_ord(grow[m]) >> 24;
        unsigned int am = __activemask();
        unsigned int mk = __match_any_sync(am, bin);
        if (lane == __ffs(mk) - 1) atomicAdd(&h0[bin], __popc(mk));
    }
    __syncthreads();

    // ---- inclusive suffix sum h0 -> src ----
    unsigned int* src = h0; unsigned int* dst = h1;
    #pragma unroll
    for (int off = 1; off < 256; off <<= 1) {
        dst[tid] = src[tid] + ((tid + off < 256) ? src[tid + off] : 0u);
        __syncthreads();
        unsigned int* t = src; src = dst; dst = t;
    }
    {
        unsigned int above = (tid < 255) ? src[tid + 1] : 0u;
        if (src[tid] >= (unsigned)TOPK && above < (unsigned)TOPK) s_b = tid;
    }
    __syncthreads();
    int bsel = s_b;

    // ---- level 0 collect: winners (byte > bsel), equals (byte == bsel) ----
    for (int m = tid; m < cnt; m += 256) {
        float v = grow[m];
        unsigned int u = f2u_ord(v);
        int byt = (int)(u >> 24);
        if (byt > bsel) {
            int p = atomicAdd(&s_nwin, 1);
            wini[p] = m; winv[p] = v;
        } else if (byt == bsel) {
            int p = atomicAdd(&s_neq[0], 1);
            if (p < CAP2) { equ[0][p] = u; eqi[0][p] = m; }
        }
    }
    __syncthreads();

    if (s_neq[0] <= CAP2) {
        int cur = 0;
        #pragma unroll
        for (int lvl = 1; lvl < 4; lvl++) {
            int sh = 24 - 8 * lvl;
            int ne = s_neq[cur];
            int krem = TOPK - s_nwin;
            if (ne == krem) {   // equals exactly fill the remainder
                for (int i = tid; i < ne; i += 256) {
                    int p = atomicAdd(&s_nwin, 1);
                    wini[p] = eqi[cur][i]; winv[p] = u2f_ord(equ[cur][i]);
                }
                if (tid == 0) s_neq[cur] = 0;
                __syncthreads();
                break;
            }
            h0[tid] = 0u;
            if (tid == 0) s_neq[cur ^ 1] = 0;
            __syncthreads();
            for (int i = tid; i < ne; i += 256) {
                unsigned int bin = (equ[cur][i] >> sh) & 0xFFu;
                unsigned int am = __activemask();
                unsigned int mk = __match_any_sync(am, bin);
                if (lane == __ffs(mk) - 1) atomicAdd(&h0[bin], __popc(mk));
            }
            __syncthreads();
            src = h0; dst = h1;
            #pragma unroll
            for (int off = 1; off < 256; off <<= 1) {
                dst[tid] = src[tid] + ((tid + off < 256) ? src[tid + off] : 0u);
                __syncthreads();
                unsigned int* t = src; src = dst; dst = t;
            }
            {
                unsigned int above = (tid < 255) ? src[tid + 1] : 0u;
                if (src[tid] >= (unsigned)krem && above < (unsigned)krem) s_b = tid;
            }
            __syncthreads();
            int bs = s_b;
            for (int i = tid; i < ne; i += 256) {
                unsigned int u = equ[cur][i];
                int byt = (int)((u >> sh) & 0xFFu);
                if (byt > bs) {
                    int p = atomicAdd(&s_nwin, 1);
                    wini[p] = eqi[cur][i]; winv[p] = u2f_ord(u);
                } else if (byt == bs) {
                    int p = atomicAdd(&s_neq[cur ^ 1], 1);
                    equ[cur ^ 1][p] = u; eqi[cur ^ 1][p] = eqi[cur][i];
                }
            }
            __syncthreads();
            cur ^= 1;
        }

        // ---- final equals: identical values; take lowest indices ----
        {
            int ne = s_neq[cur];
            int krem = TOPK - s_nwin;
            if (krem > 0 && ne > 0) {
                if (ne == krem) {
                    for (int i = tid; i < ne; i += 256) {
                        int p = atomicAdd(&s_nwin, 1);
                        wini[p] = eqi[cur][i]; winv[p] = u2f_ord(equ[cur][i]);
                    }
                } else if (warp == 0) {
                    float val = u2f_ord(equ[cur][0]);
                    for (int r = 0; r < krem; r++) {
                        int mn = 0x7FFFFFFF;
                        for (int i = lane; i < ne; i += 32) mn = min(mn, eqi[cur][i]);
                        #pragma unroll
                        for (int off = 16; off > 0; off >>= 1)
                            mn = min(mn, __shfl_xor_sync(0xFFFFFFFFu, mn, off));
                        for (int i = lane; i < ne; i += 32)
                            if (eqi[cur][i] == mn) eqi[cur][i] = 0x7FFFFFFF;
                        if (lane == 0) {
                            int p = s_nwin + r;
                            wini[p] = mn; winv[p] = val;
                        }
                    }
                }
            }
        }
    } else {
        // ---- fallback (overflow; adversarial only): iterative argmax ----
        if (tid == 0) s_nwin = TOPK;
        for (int k = 0; k < TOPK; k++) {
            float best = -FLT_MAX; int bidx = 0x7FFFFFFF;
            for (int m = tid; m < cnt; m += 256) {
                float v = grow[m];
                if (v > best || (v == best && m < bidx)) { best = v; bidx = m; }
            }
            #pragma unroll
            for (int off = 16; off > 0; off >>= 1) {
                float ov = __shfl_down_sync(0xFFFFFFFFu, best, off);
                int   oi = __shfl_down_sync(0xFFFFFFFFu, bidx, off);
                if (ov > best || (ov == best && oi < bidx)) { best = ov; bidx = oi; }
            }
            if (lane == 0) { rv[warp] = best; ri[warp] = bidx; }
            __syncthreads();
            if (tid == 0) {
                float bb = rv[0]; int bi = ri[0];
                #pragma unroll
                for (int w = 1; w < 8; w++)
                    if (rv[w] > bb || (rv[w] == bb && ri[w] < bi)) { bb = rv[w]; bi = ri[w]; }
                winv[k] = bb; wini[k] = bi; grow[bi] = -FLT_MAX;
            }
            __syncthreads();
        }
    }
    __syncthreads();

    // ---- map candidate position -> original row index ----
    if (tid < TOPK) wini[tid] = g_cidx[min(wini[tid], cnt - 1)];
    __syncthreads();

    // ---- softmax over the 32 selected logits (order-invariant) ----
    if (tid < 32) {
        float v = winv[tid];
        float mx = v;
        #pragma unroll
        for (int off = 16; off > 0; off >>= 1)
            mx = fmaxf(mx, __shfl_xor_sync(0xFFFFFFFFu, mx, off));
        float e = expf(v - mx);
        float ssum = e;
        #pragma unroll
        for (int off = 16; off > 0; off >>= 1)
            ssum += __shfl_xor_sync(0xFFFFFFFFu, ssum, off);
        winv[tid] = e / ssum;
    }
    __syncthreads();

    // ---- gather: out[b, d] = sum_k attn[k] * V[idx_k, d]   (tid == d) ----
    float acc = 0.0f;
    #pragma unroll
    for (int k = 0; k < TOPK; k++)
        acc += winv[k] * Vbank[(size_t)wini[k] * DIM + tid];
    out[b * DIM + tid] = acc;
}

// ---------------------------------------------------------------------------
extern "C" void kernel_launch(void* const* d_in, const int* in_sizes, int n_in,
                              void* d_out, int out_size) {
    const float* query = (const float*)d_in[0];
    const float* Kbank = (const float*)d_in[1];
    const float* Vbank = (const float*)d_in[2];
    const float* times = (const float*)d_in[3];
    const float* qtime = (const float*)d_in[4];
    float* out = (float*)d_out;

    int B = in_sizes[0] / DIM;
    int N = in_sizes[3];

    int logits_smem = (DIM * QG + DIM * CG) * (int)sizeof(float);  // 96 KB
    cudaFuncSetAttribute(k_logits, cudaFuncAttributeMaxDynamicSharedMemorySize,
                         logits_smem);

    k_init<<<1, 32>>>();
    k_pre<<<PRE_BLOCKS, 256>>>(times, qtime, query, N, B);
    dim3 g3(74, (B + QG - 1) / QG);       // 296 blocks = 2/SM
    k_logits<<<g3, 128, logits_smem>>>(Kbank, B);
    k_select<<<B, 256>>>(Vbank, out, B);
}